// round 1
// baseline (speedup 1.0000x reference)
#include <cuda_runtime.h>
#include <cuda_bf16.h>
#include <cstdint>

// ---------------------------------------------------------------------------
// Scratch (device globals: no allocation allowed in kernel_launch)
// ---------------------------------------------------------------------------
__device__ float g_s1[1024 * 36 * 32 * 32];   // shared branch after conv1+pool
__device__ float g_s2[1024 * 36 * 16 * 16];   // after conv2+pool
__device__ float g_s3[1024 * 36 * 8 * 8];     // after conv3+pool (flatten 2304)
__device__ float g_h [1024 * 12];             // shared fc out
__device__ float g_p1[1024 * 12 * 32 * 32];   // private conv+pool (flatten 12288)
__device__ float g_pf[1024 * 12];             // private fc out

// ---------------------------------------------------------------------------
// Fused conv3x3(SAME) + bias + activation + maxpool2, C_in=3, H=64 -> 32x32
// One block per image. Padded input tile (3 x 66 x 66) + weights in SMEM.
// Each thread: 4 pooled positions, loops all OC with 4x4 patch in registers.
// ---------------------------------------------------------------------------
template <int OC, bool LEAKY, bool USE_DOM>
__global__ void conv_in_k(const float* __restrict__ x,
                          const float* __restrict__ W,
                          const float* __restrict__ bias,
                          const int*   __restrict__ dom,
                          float* __restrict__ out) {
    extern __shared__ float smem[];
    float* in_s = smem;               // 3*66*66 = 13068
    float* w_s  = smem + 13068;       // OC*27
    float* b_s  = w_s + OC * 27;      // OC

    int b = blockIdx.x;
    if (USE_DOM) {
        int d = *dom;
        W    += d * OC * 27;
        bias += d * OC;
    }

    for (int i = threadIdx.x; i < 13068; i += 256) in_s[i] = 0.f;
    __syncthreads();
    const float* src = x + (size_t)b * 3 * 64 * 64;
    for (int i = threadIdx.x; i < 3 * 64 * 64; i += 256) {
        int c = i >> 12, r = (i >> 6) & 63, col = i & 63;
        in_s[c * 4356 + (r + 1) * 66 + (col + 1)] = src[i];
    }
    for (int i = threadIdx.x; i < OC * 27; i += 256) w_s[i] = W[i];
    if (threadIdx.x < OC) b_s[threadIdx.x] = bias[threadIdx.x];
    __syncthreads();

    #pragma unroll
    for (int pp = 0; pp < 4; pp++) {
        int p  = threadIdx.x + pp * 256;      // 0..1023
        int py = p >> 5, px = p & 31;
        float pv[3][4][4];
        #pragma unroll
        for (int c = 0; c < 3; c++) {
            const float* ip = in_s + c * 4356 + (2 * py) * 66 + 2 * px;
            #pragma unroll
            for (int r = 0; r < 4; r++)
                #pragma unroll
                for (int cc = 0; cc < 4; cc++)
                    pv[c][r][cc] = ip[r * 66 + cc];
        }
        for (int oc = 0; oc < OC; oc++) {
            float a0 = 0.f, a1 = 0.f, a2 = 0.f, a3 = 0.f;
            const float* wp = w_s + oc * 27;
            #pragma unroll
            for (int c = 0; c < 3; c++)
                #pragma unroll
                for (int ky = 0; ky < 3; ky++)
                    #pragma unroll
                    for (int kx = 0; kx < 3; kx++) {
                        float wv = wp[c * 9 + ky * 3 + kx];
                        a0 = fmaf(pv[c][ky    ][kx    ], wv, a0);
                        a1 = fmaf(pv[c][ky    ][kx + 1], wv, a1);
                        a2 = fmaf(pv[c][ky + 1][kx    ], wv, a2);
                        a3 = fmaf(pv[c][ky + 1][kx + 1], wv, a3);
                    }
            float m = fmaxf(fmaxf(a0, a1), fmaxf(a2, a3)) + b_s[oc];
            float r = LEAKY ? (m > 0.f ? m : 0.001f * m) : fmaxf(m, 0.f);
            out[(((size_t)b * OC + oc) << 10) + (py << 5) + px] = r;
        }
    }
}

// ---------------------------------------------------------------------------
// Fused conv3x3(SAME, 36->36) + bias + relu + maxpool2, templated on H.
// One block per image; full padded input (36 x (H+2)^2) + all weights in SMEM.
// ---------------------------------------------------------------------------
template <int H>
__global__ void conv_hid_k(const float* __restrict__ in,
                           const float* __restrict__ W,
                           const float* __restrict__ bias,
                           float* __restrict__ out) {
    constexpr int OUTD   = H / 2;
    constexpr int P      = OUTD * OUTD;       // 256 (H=32) or 64 (H=16)
    constexpr int IP     = H + 2;
    constexpr int GROUPS = 256 / P;           // 1 or 4
    constexpr int OCPG   = 36 / GROUPS;       // 36 or 9
    constexpr int CH     = (H == 32) ? 6 : 9; // oc chunk per register tile

    extern __shared__ float smem[];
    float* in_s = smem;                       // 36*IP*IP
    float* w_s  = smem + 36 * IP * IP;        // 36*36*9
    float* b_s  = w_s + 36 * 324;

    int b = blockIdx.x;
    for (int i = threadIdx.x; i < 36 * IP * IP; i += 256) in_s[i] = 0.f;
    __syncthreads();
    const float* src = in + (size_t)b * 36 * H * H;
    for (int i = threadIdx.x; i < 36 * H * H; i += 256) {
        int c = i / (H * H), r = (i / H) % H, col = i % H;
        in_s[c * IP * IP + (r + 1) * IP + (col + 1)] = src[i];
    }
    for (int i = threadIdx.x; i < 36 * 324; i += 256) w_s[i] = W[i];
    if (threadIdx.x < 36) b_s[threadIdx.x] = bias[threadIdx.x];
    __syncthreads();

    int p  = threadIdx.x % P;
    int g  = threadIdx.x / P;
    int py = p / OUTD, px = p % OUTD;
    int r0 = 2 * py, c0 = 2 * px;

    for (int oc0 = g * OCPG; oc0 < (g + 1) * OCPG; oc0 += CH) {
        float acc[CH][4];
        #pragma unroll
        for (int j = 0; j < CH; j++)
            #pragma unroll
            for (int q = 0; q < 4; q++) acc[j][q] = 0.f;

        for (int ic = 0; ic < 36; ic++) {
            float pv[4][4];
            const float* ip = in_s + ic * IP * IP + r0 * IP + c0;
            #pragma unroll
            for (int r = 0; r < 4; r++)
                #pragma unroll
                for (int cc = 0; cc < 4; cc++) pv[r][cc] = ip[r * IP + cc];
            #pragma unroll
            for (int j = 0; j < CH; j++) {
                const float* wp = w_s + ((oc0 + j) * 36 + ic) * 9;
                #pragma unroll
                for (int ky = 0; ky < 3; ky++)
                    #pragma unroll
                    for (int kx = 0; kx < 3; kx++) {
                        float wv = wp[ky * 3 + kx];
                        acc[j][0] = fmaf(pv[ky    ][kx    ], wv, acc[j][0]);
                        acc[j][1] = fmaf(pv[ky    ][kx + 1], wv, acc[j][1]);
                        acc[j][2] = fmaf(pv[ky + 1][kx    ], wv, acc[j][2]);
                        acc[j][3] = fmaf(pv[ky + 1][kx + 1], wv, acc[j][3]);
                    }
            }
        }
        #pragma unroll
        for (int j = 0; j < CH; j++) {
            float m = fmaxf(fmaxf(acc[j][0], acc[j][1]),
                            fmaxf(acc[j][2], acc[j][3])) + b_s[oc0 + j];
            out[(((size_t)b * 36 + oc0 + j) * OUTD + py) * OUTD + px] = fmaxf(m, 0.f);
        }
    }
}

// ---------------------------------------------------------------------------
// FC: [B,2304] @ [12,2304]^T + b, relu.  One block per sample, warp per output.
// ---------------------------------------------------------------------------
__global__ void fc_shared_k(const float* __restrict__ in,
                            const float* __restrict__ W,
                            const float* __restrict__ bias,
                            float* __restrict__ out) {
    int b = blockIdx.x, w = threadIdx.x >> 5, l = threadIdx.x & 31;
    const float4* xr = (const float4*)(in + (size_t)b * 2304);
    const float4* wr = (const float4*)(W + (size_t)w * 2304);
    float s = 0.f;
    for (int k = l; k < 576; k += 32) {
        float4 a = xr[k], c = wr[k];
        s += a.x * c.x + a.y * c.y + a.z * c.z + a.w * c.w;
    }
    #pragma unroll
    for (int o = 16; o; o >>= 1) s += __shfl_xor_sync(0xffffffffu, s, o);
    if (!l) out[b * 12 + w] = fmaxf(s + bias[w], 0.f);
}

// FC: [B,12288] @ Pl_W[dom][12,12288]^T + Pl_b[dom]  (no activation)
__global__ void fc_priv_k(const float* __restrict__ in,
                          const float* __restrict__ W,
                          const float* __restrict__ bias,
                          const int*   __restrict__ dom,
                          float* __restrict__ out) {
    int d = *dom;
    int b = blockIdx.x, w = threadIdx.x >> 5, l = threadIdx.x & 31;
    const float4* xr = (const float4*)(in + (size_t)b * 12288);
    const float4* wr = (const float4*)(W + ((size_t)d * 12 + w) * 12288);
    float s = 0.f;
    for (int k = l; k < 3072; k += 32) {
        float4 a = xr[k], c = wr[k];
        s += a.x * c.x + a.y * c.y + a.z * c.z + a.w * c.w;
    }
    #pragma unroll
    for (int o = 16; o; o >>= 1) s += __shfl_xor_sync(0xffffffffu, s, o);
    if (!l) out[b * 12 + w] = s + bias[d * 12 + w];
}

// ---------------------------------------------------------------------------
// Per-sample task-routed heads. One thread per sample, all-register MLP.
// ---------------------------------------------------------------------------
__global__ void heads_k(const float* __restrict__ h, const float* __restrict__ p,
                        const int* __restrict__ tt,
                        const float* __restrict__ W1, const float* __restrict__ b1,
                        const float* __restrict__ W2, const float* __restrict__ b2,
                        const float* __restrict__ W3, const float* __restrict__ b3,
                        float* __restrict__ out) {
    int bi = blockIdx.x * blockDim.x + threadIdx.x;
    if (bi >= 1024) return;
    int t = tt[bi];
    float x[24];
    #pragma unroll
    for (int i = 0; i < 12; i++) { x[i] = h[bi * 12 + i]; x[12 + i] = p[bi * 12 + i]; }

    float h1[28];
    const float* w1 = W1 + t * 28 * 24;
    #pragma unroll
    for (int i = 0; i < 28; i++) {
        float s = b1[t * 28 + i];
        #pragma unroll
        for (int j = 0; j < 24; j++) s = fmaf(w1[i * 24 + j], x[j], s);
        h1[i] = fmaxf(s, 0.f);
    }
    float h2[14];
    const float* w2 = W2 + t * 14 * 28;
    #pragma unroll
    for (int i = 0; i < 14; i++) {
        float s = b2[t * 14 + i];
        #pragma unroll
        for (int j = 0; j < 28; j++) s = fmaf(w2[i * 28 + j], h1[j], s);
        h2[i] = fmaxf(s, 0.f);
    }
    const float* w3 = W3 + t * 5 * 14;
    #pragma unroll
    for (int i = 0; i < 5; i++) {
        float s = b3[t * 5 + i];
        #pragma unroll
        for (int j = 0; j < 14; j++) s = fmaf(w3[i * 14 + j], h2[j], s);
        out[bi * 5 + i] = s;
    }
}

// ---------------------------------------------------------------------------
// Launch
// ---------------------------------------------------------------------------
extern "C" void kernel_launch(void* const* d_in, const int* in_sizes, int n_in,
                              void* d_out, int out_size) {
    const float* x_s      = (const float*)d_in[0];
    const float* x_p      = (const float*)d_in[1];
    const int*   tt       = (const int*)  d_in[2];
    const int*   dom      = (const int*)  d_in[3];
    const float* Ws_in_W  = (const float*)d_in[4];
    const float* Ws_in_b  = (const float*)d_in[5];
    const float* Ws_hid_W = (const float*)d_in[6];
    const float* Ws_hid_b = (const float*)d_in[7];
    const float* Ws_fc_W  = (const float*)d_in[8];
    const float* Ws_fc_b  = (const float*)d_in[9];
    const float* Pc_W     = (const float*)d_in[10];
    const float* Pc_b     = (const float*)d_in[11];
    const float* Pl_W     = (const float*)d_in[12];
    const float* Pl_b     = (const float*)d_in[13];
    const float* H1W      = (const float*)d_in[14];
    const float* H1b      = (const float*)d_in[15];
    const float* H2W      = (const float*)d_in[16];
    const float* H2b      = (const float*)d_in[17];
    const float* H3W      = (const float*)d_in[18];
    const float* H3b      = (const float*)d_in[19];
    float* out = (float*)d_out;

    float *s1, *s2, *s3, *hb, *p1, *pf;
    cudaGetSymbolAddress((void**)&s1, g_s1);
    cudaGetSymbolAddress((void**)&s2, g_s2);
    cudaGetSymbolAddress((void**)&s3, g_s3);
    cudaGetSymbolAddress((void**)&hb, g_h);
    cudaGetSymbolAddress((void**)&p1, g_p1);
    cudaGetSymbolAddress((void**)&pf, g_pf);

    const int SM_IN36 = (13068 + 36 * 27 + 36) * 4;               // 56304
    const int SM_IN12 = (13068 + 12 * 27 + 12) * 4;               // 53616
    const int SM_H32  = (36 * 34 * 34 + 36 * 324 + 36) * 4;       // 213264
    const int SM_H16  = (36 * 18 * 18 + 36 * 324 + 36) * 4;       // 93456

    cudaFuncSetAttribute((const void*)conv_in_k<36, false, false>,
                         cudaFuncAttributeMaxDynamicSharedMemorySize, SM_IN36);
    cudaFuncSetAttribute((const void*)conv_in_k<12, true, true>,
                         cudaFuncAttributeMaxDynamicSharedMemorySize, SM_IN12);
    cudaFuncSetAttribute((const void*)conv_hid_k<32>,
                         cudaFuncAttributeMaxDynamicSharedMemorySize, SM_H32);
    cudaFuncSetAttribute((const void*)conv_hid_k<16>,
                         cudaFuncAttributeMaxDynamicSharedMemorySize, SM_H16);

    conv_in_k<36, false, false><<<1024, 256, SM_IN36>>>(x_s, Ws_in_W, Ws_in_b, nullptr, s1);
    conv_hid_k<32><<<1024, 256, SM_H32>>>(s1, Ws_hid_W, Ws_hid_b, s2);
    conv_hid_k<16><<<1024, 256, SM_H16>>>(s2, Ws_hid_W, Ws_hid_b, s3);
    conv_in_k<12, true, true><<<1024, 256, SM_IN12>>>(x_p, Pc_W, Pc_b, dom, p1);
    fc_shared_k<<<1024, 384>>>(s3, Ws_fc_W, Ws_fc_b, hb);
    fc_priv_k<<<1024, 384>>>(p1, Pl_W, Pl_b, dom, pf);
    heads_k<<<4, 256>>>(hb, pf, tt, H1W, H1b, H2W, H2b, H3W, H3b, out);
}

// round 5
// speedup vs baseline: 1.1040x; 1.1040x over previous
#include <cuda_runtime.h>
#include <cuda_bf16.h>
#include <cstdint>

using u64 = unsigned long long;

// ---------------------------------------------------------------------------
// Packed f32x2 helpers (sm_103a FFMA2 path — only reachable via PTX)
// ---------------------------------------------------------------------------
__device__ __forceinline__ u64 pk2(float lo, float hi) {
    u64 r; asm("mov.b64 %0,{%1,%2};" : "=l"(r) : "f"(lo), "f"(hi)); return r;
}
__device__ __forceinline__ u64 dup2(float v) { return pk2(v, v); }
__device__ __forceinline__ u64 ffma2(u64 a, u64 b, u64 c) {
    u64 d; asm("fma.rn.f32x2 %0,%1,%2,%3;" : "=l"(d) : "l"(a), "l"(b), "l"(c)); return d;
}
__device__ __forceinline__ float2 un2(u64 a) {
    float2 f; asm("mov.b64 {%0,%1},%2;" : "=f"(f.x), "=f"(f.y) : "l"(a)); return f;
}

// ---------------------------------------------------------------------------
// Scratch
// ---------------------------------------------------------------------------
__device__ float g_s1[1024 * 36 * 32 * 32];
__device__ float g_s2[1024 * 36 * 16 * 16];
__device__ float g_s3[1024 * 36 * 8 * 8];
__device__ float g_h [1024 * 12];
__device__ float g_p1[1024 * 12 * 32 * 32];
__device__ float g_pf[1024 * 12];

// ---------------------------------------------------------------------------
// Fused conv3x3(SAME,Cin=3,H=64)+bias+act+maxpool2 -> [OC,32,32]
// oc-pair packed f32x2. Each thread: 1x2 pooled block (2x4 conv outputs).
// Weights permuted in smem: w_s[(c*9+k)*OC + oc] -> LDS.64 gives (w_j, w_j+1).
// ---------------------------------------------------------------------------
template <int OC, bool LEAKY, bool USE_DOM>
__global__ __launch_bounds__(256) void conv_in_k(const float* __restrict__ x,
                                                 const float* __restrict__ W,
                                                 const float* __restrict__ bias,
                                                 const int*   __restrict__ dom,
                                                 float* __restrict__ out) {
    constexpr int IP = 66;
    constexpr int NCH = OC / 6;                 // chunks of 3 oc-pairs
    extern __shared__ float smem[];
    float* in_s = smem;                          // 3*66*66 = 13068
    float* w_s  = smem + 13068;                  // 27*OC (permuted)
    float* b_s  = w_s + 27 * OC;

    int b = blockIdx.x;
    if (USE_DOM) { int d = *dom; W += d * OC * 27; bias += d * OC; }

    for (int i = threadIdx.x; i < 3 * IP * IP; i += 256) in_s[i] = 0.f;
    __syncthreads();
    const float* src = x + (size_t)b * 3 * 64 * 64;
    for (int i = threadIdx.x; i < 3 * 64 * 64; i += 256) {
        int c = i >> 12, r = (i >> 6) & 63, col = i & 63;
        in_s[c * (IP * IP) + (r + 1) * IP + (col + 1)] = src[i];
    }
    for (int i = threadIdx.x; i < OC * 27; i += 256) {
        int oc = i / 27, rem = i % 27;           // rem = c*9+k
        w_s[rem * OC + oc] = W[i];
    }
    if (threadIdx.x < OC) b_s[threadIdx.x] = bias[threadIdx.x];
    __syncthreads();

    #pragma unroll
    for (int pp = 0; pp < 2; pp++) {
        int slot = pp * 256 + threadIdx.x;       // 0..511
        int py  = slot >> 4;                      // 0..31
        int px0 = (slot & 15) << 1;               // 0,2,..,30
        int r0 = 2 * py, c0 = 2 * px0;

        for (int ch = 0; ch < NCH; ch++) {
            u64 acc[3][2][4];
            #pragma unroll
            for (int p = 0; p < 3; p++)
                #pragma unroll
                for (int r = 0; r < 2; r++)
                    #pragma unroll
                    for (int c = 0; c < 4; c++) acc[p][r][c] = 0ull;

            #pragma unroll
            for (int ic = 0; ic < 3; ic++) {
                u64 pvd[4][6];
                const float* ip = in_s + ic * (IP * IP) + r0 * IP + c0;
                #pragma unroll
                for (int r = 0; r < 4; r++) {
                    float2 q0 = *(const float2*)(ip + r * IP);
                    float2 q1 = *(const float2*)(ip + r * IP + 2);
                    float2 q2 = *(const float2*)(ip + r * IP + 4);
                    pvd[r][0] = dup2(q0.x); pvd[r][1] = dup2(q0.y);
                    pvd[r][2] = dup2(q1.x); pvd[r][3] = dup2(q1.y);
                    pvd[r][4] = dup2(q2.x); pvd[r][5] = dup2(q2.y);
                }
                #pragma unroll
                for (int p = 0; p < 3; p++) {
                    int j = (ch * 3 + p) * 2;
                    #pragma unroll
                    for (int ky = 0; ky < 3; ky++)
                        #pragma unroll
                        for (int kx = 0; kx < 3; kx++) {
                            u64 w = *(const u64*)(w_s + (ic * 9 + ky * 3 + kx) * OC + j);
                            #pragma unroll
                            for (int r = 0; r < 2; r++)
                                #pragma unroll
                                for (int c = 0; c < 4; c++)
                                    acc[p][r][c] = ffma2(pvd[r + ky][c + kx], w, acc[p][r][c]);
                        }
                }
            }
            #pragma unroll
            for (int p = 0; p < 3; p++) {
                int j = (ch * 3 + p) * 2;
                float2 v[2][4];
                #pragma unroll
                for (int r = 0; r < 2; r++)
                    #pragma unroll
                    for (int c = 0; c < 4; c++) v[r][c] = un2(acc[p][r][c]);
                #pragma unroll
                for (int cc = 0; cc < 2; cc++) {
                    float mlo = fmaxf(fmaxf(v[0][2 * cc].x, v[0][2 * cc + 1].x),
                                      fmaxf(v[1][2 * cc].x, v[1][2 * cc + 1].x)) + b_s[j];
                    float mhi = fmaxf(fmaxf(v[0][2 * cc].y, v[0][2 * cc + 1].y),
                                      fmaxf(v[1][2 * cc].y, v[1][2 * cc + 1].y)) + b_s[j + 1];
                    float rlo = LEAKY ? (mlo > 0.f ? mlo : 0.001f * mlo) : fmaxf(mlo, 0.f);
                    float rhi = LEAKY ? (mhi > 0.f ? mhi : 0.001f * mhi) : fmaxf(mhi, 0.f);
                    out[(((size_t)b * OC + j)     << 10) + (py << 5) + px0 + cc] = rlo;
                    out[(((size_t)b * OC + j + 1) << 10) + (py << 5) + px0 + cc] = rhi;
                }
            }
        }
    }
}

// ---------------------------------------------------------------------------
// Fused conv3x3(SAME,36->36)+bias+relu+maxpool2, oc-pair packed f32x2.
// GROUPS split output channels; each thread: 1x2 pooled block.
// ---------------------------------------------------------------------------
template <int H, int GROUPS>
__global__ __launch_bounds__(GROUPS*(H/4)*(H/2)) void conv_hid_k(
        const float* __restrict__ in,
        const float* __restrict__ W,
        const float* __restrict__ bias,
        float* __restrict__ out) {
    constexpr int OUTD  = H / 2;
    constexpr int HX    = OUTD / 2;
    constexpr int SLOTS = HX * OUTD;
    constexpr int T     = GROUPS * SLOTS;
    constexpr int IP    = H + 2;
    constexpr int PPG   = 18 / GROUPS;           // oc-pairs per group
    constexpr int NCH   = PPG / 3;               // chunks of 3 pairs

    extern __shared__ float smem[];
    float* in_s = smem;                          // 36*IP*IP
    float* w_s  = smem + 36 * IP * IP;           // 36*9*36 permuted [ic][k][oc]
    float* b_s  = w_s + 36 * 324;

    int b = blockIdx.x;
    for (int i = threadIdx.x; i < 36 * IP * IP; i += T) in_s[i] = 0.f;
    __syncthreads();
    const float* src = in + (size_t)b * 36 * H * H;
    for (int i = threadIdx.x; i < 36 * H * H; i += T) {
        int c = i / (H * H), r = (i / H) % H, col = i % H;
        in_s[c * IP * IP + (r + 1) * IP + (col + 1)] = src[i];
    }
    for (int i = threadIdx.x; i < 36 * 324; i += T) {
        int oc = i / 324, rem = i % 324;          // rem = ic*9+k
        w_s[rem * 36 + oc] = W[i];
    }
    if (threadIdx.x < 36) b_s[threadIdx.x] = bias[threadIdx.x];
    __syncthreads();

    int slot = threadIdx.x % SLOTS;
    int g    = threadIdx.x / SLOTS;
    int py   = slot / HX;
    int px0  = 2 * (slot % HX);
    int r0 = 2 * py, c0 = 2 * px0;

    for (int ch = 0; ch < NCH; ch++) {
        int pb = g * PPG + ch * 3;               // first oc-pair of chunk
        u64 acc[3][2][4];
        #pragma unroll
        for (int p = 0; p < 3; p++)
            #pragma unroll
            for (int r = 0; r < 2; r++)
                #pragma unroll
                for (int c = 0; c < 4; c++) acc[p][r][c] = 0ull;

        for (int ic = 0; ic < 36; ic++) {
            u64 pvd[4][6];
            const float* ip = in_s + ic * (IP * IP) + r0 * IP + c0;
            #pragma unroll
            for (int r = 0; r < 4; r++) {
                float2 q0 = *(const float2*)(ip + r * IP);
                float2 q1 = *(const float2*)(ip + r * IP + 2);
                float2 q2 = *(const float2*)(ip + r * IP + 4);
                pvd[r][0] = dup2(q0.x); pvd[r][1] = dup2(q0.y);
                pvd[r][2] = dup2(q1.x); pvd[r][3] = dup2(q1.y);
                pvd[r][4] = dup2(q2.x); pvd[r][5] = dup2(q2.y);
            }
            const float* wb = w_s + ic * 9 * 36;
            #pragma unroll
            for (int p = 0; p < 3; p++) {
                int j = (pb + p) * 2;
                #pragma unroll
                for (int ky = 0; ky < 3; ky++)
                    #pragma unroll
                    for (int kx = 0; kx < 3; kx++) {
                        u64 w = *(const u64*)(wb + (ky * 3 + kx) * 36 + j);
                        #pragma unroll
                        for (int r = 0; r < 2; r++)
                            #pragma unroll
                            for (int c = 0; c < 4; c++)
                                acc[p][r][c] = ffma2(pvd[r + ky][c + kx], w, acc[p][r][c]);
                    }
            }
        }
        #pragma unroll
        for (int p = 0; p < 3; p++) {
            int j = (pb + p) * 2;
            float2 v[2][4];
            #pragma unroll
            for (int r = 0; r < 2; r++)
                #pragma unroll
                for (int c = 0; c < 4; c++) v[r][c] = un2(acc[p][r][c]);
            #pragma unroll
            for (int cc = 0; cc < 2; cc++) {
                float mlo = fmaxf(fmaxf(v[0][2 * cc].x, v[0][2 * cc + 1].x),
                                  fmaxf(v[1][2 * cc].x, v[1][2 * cc + 1].x)) + b_s[j];
                float mhi = fmaxf(fmaxf(v[0][2 * cc].y, v[0][2 * cc + 1].y),
                                  fmaxf(v[1][2 * cc].y, v[1][2 * cc + 1].y)) + b_s[j + 1];
                out[(((size_t)b * 36 + j)     * OUTD + py) * OUTD + px0 + cc] = fmaxf(mlo, 0.f);
                out[(((size_t)b * 36 + j + 1) * OUTD + py) * OUTD + px0 + cc] = fmaxf(mhi, 0.f);
            }
        }
    }
}

// ---------------------------------------------------------------------------
// Batched FC: 16 samples/block, W staged in SMEM (kills redundant L2 traffic).
// 16 threads per sample (half-warp), K split across them, shfl reduce.
// ---------------------------------------------------------------------------
template <int K, int KC, bool RELU, bool USE_DOM>
__global__ __launch_bounds__(256) void fc_batch_k(const float* __restrict__ in,
                                                  const float* __restrict__ W,
                                                  const float* __restrict__ bias,
                                                  const int*   __restrict__ dom,
                                                  float* __restrict__ out) {
    extern __shared__ float ws[];                // [12][KC]
    if (USE_DOM) { int d = *dom; W += (size_t)d * 12 * K; bias += d * 12; }

    int tid  = threadIdx.x;
    int lane = tid & 31;
    int l16  = lane & 15;
    int s    = (tid >> 5) * 2 + (lane >> 4);     // local sample 0..15
    const float* xp = in + ((size_t)blockIdx.x * 16 + s) * K;

    float acc[12];
    #pragma unroll
    for (int o = 0; o < 12; o++) acc[o] = 0.f;

    for (int kc0 = 0; kc0 < K; kc0 += KC) {
        __syncthreads();
        for (int i = tid; i < 12 * KC; i += 256) {
            int o = i / KC, k = i % KC;
            ws[i] = W[(size_t)o * K + kc0 + k];
        }
        __syncthreads();
        constexpr int NI = KC / 64;              // float4 iterations per thread
        #pragma unroll 4
        for (int i = 0; i < NI; i++) {
            int k4 = l16 + i * 16;
            float4 xa = ((const float4*)(xp + kc0))[k4];
            #pragma unroll
            for (int o = 0; o < 12; o++) {
                float4 wa = ((const float4*)(ws + o * KC))[k4];
                acc[o] = fmaf(xa.x, wa.x, fmaf(xa.y, wa.y,
                          fmaf(xa.z, wa.z, fmaf(xa.w, wa.w, acc[o]))));
            }
        }
    }
    #pragma unroll
    for (int o = 0; o < 12; o++) {
        #pragma unroll
        for (int off = 8; off; off >>= 1)
            acc[o] += __shfl_down_sync(0xffffffffu, acc[o], off, 16);
    }
    if (l16 == 0) {
        size_t sg = (size_t)blockIdx.x * 16 + s;
        #pragma unroll
        for (int o = 0; o < 12; o++) {
            float v = acc[o] + bias[o];
            out[sg * 12 + o] = RELU ? fmaxf(v, 0.f) : v;
        }
    }
}

// ---------------------------------------------------------------------------
// Per-sample task-routed heads (unchanged — already negligible).
// ---------------------------------------------------------------------------
__global__ void heads_k(const float* __restrict__ h, const float* __restrict__ p,
                        const int* __restrict__ tt,
                        const float* __restrict__ W1, const float* __restrict__ b1,
                        const float* __restrict__ W2, const float* __restrict__ b2,
                        const float* __restrict__ W3, const float* __restrict__ b3,
                        float* __restrict__ out) {
    int bi = blockIdx.x * blockDim.x + threadIdx.x;
    if (bi >= 1024) return;
    int t = tt[bi];
    float x[24];
    #pragma unroll
    for (int i = 0; i < 12; i++) { x[i] = h[bi * 12 + i]; x[12 + i] = p[bi * 12 + i]; }
    float h1[28];
    const float* w1 = W1 + t * 28 * 24;
    #pragma unroll
    for (int i = 0; i < 28; i++) {
        float s = b1[t * 28 + i];
        #pragma unroll
        for (int j = 0; j < 24; j++) s = fmaf(w1[i * 24 + j], x[j], s);
        h1[i] = fmaxf(s, 0.f);
    }
    float h2[14];
    const float* w2 = W2 + t * 14 * 28;
    #pragma unroll
    for (int i = 0; i < 14; i++) {
        float s = b2[t * 14 + i];
        #pragma unroll
        for (int j = 0; j < 28; j++) s = fmaf(w2[i * 28 + j], h1[j], s);
        h2[i] = fmaxf(s, 0.f);
    }
    const float* w3 = W3 + t * 5 * 14;
    #pragma unroll
    for (int i = 0; i < 5; i++) {
        float s = b3[t * 5 + i];
        #pragma unroll
        for (int j = 0; j < 14; j++) s = fmaf(w3[i * 14 + j], h2[j], s);
        out[bi * 5 + i] = s;
    }
}

// ---------------------------------------------------------------------------
// Launch
// ---------------------------------------------------------------------------
extern "C" void kernel_launch(void* const* d_in, const int* in_sizes, int n_in,
                              void* d_out, int out_size) {
    const float* x_s      = (const float*)d_in[0];
    const float* x_p      = (const float*)d_in[1];
    const int*   tt       = (const int*)  d_in[2];
    const int*   dom      = (const int*)  d_in[3];
    const float* Ws_in_W  = (const float*)d_in[4];
    const float* Ws_in_b  = (const float*)d_in[5];
    const float* Ws_hid_W = (const float*)d_in[6];
    const float* Ws_hid_b = (const float*)d_in[7];
    const float* Ws_fc_W  = (const float*)d_in[8];
    const float* Ws_fc_b  = (const float*)d_in[9];
    const float* Pc_W     = (const float*)d_in[10];
    const float* Pc_b     = (const float*)d_in[11];
    const float* Pl_W     = (const float*)d_in[12];
    const float* Pl_b     = (const float*)d_in[13];
    const float* H1W      = (const float*)d_in[14];
    const float* H1b      = (const float*)d_in[15];
    const float* H2W      = (const float*)d_in[16];
    const float* H2b      = (const float*)d_in[17];
    const float* H3W      = (const float*)d_in[18];
    const float* H3b      = (const float*)d_in[19];
    float* out = (float*)d_out;

    float *s1, *s2, *s3, *hb, *p1, *pf;
    cudaGetSymbolAddress((void**)&s1, g_s1);
    cudaGetSymbolAddress((void**)&s2, g_s2);
    cudaGetSymbolAddress((void**)&s3, g_s3);
    cudaGetSymbolAddress((void**)&hb, g_h);
    cudaGetSymbolAddress((void**)&p1, g_p1);
    cudaGetSymbolAddress((void**)&pf, g_pf);

    const int SM_IN36 = (13068 + 36 * 27 + 36) * 4;
    const int SM_IN12 = (13068 + 12 * 27 + 12) * 4;
    const int SM_H32  = (36 * 34 * 34 + 36 * 324 + 36) * 4;     // 213264
    const int SM_H16  = (36 * 18 * 18 + 36 * 324 + 36) * 4;     // 93456
    const int SM_FCS  = 12 * 2304 * 4;                          // 110592
    const int SM_FCP  = 12 * 2048 * 4;                          // 98304

    cudaFuncSetAttribute((const void*)conv_in_k<36, false, false>,
                         cudaFuncAttributeMaxDynamicSharedMemorySize, SM_IN36);
    cudaFuncSetAttribute((const void*)conv_in_k<12, true, true>,
                         cudaFuncAttributeMaxDynamicSharedMemorySize, SM_IN12);
    cudaFuncSetAttribute((const void*)conv_hid_k<32, 2>,
                         cudaFuncAttributeMaxDynamicSharedMemorySize, SM_H32);
    cudaFuncSetAttribute((const void*)conv_hid_k<16, 6>,
                         cudaFuncAttributeMaxDynamicSharedMemorySize, SM_H16);
    cudaFuncSetAttribute((const void*)fc_batch_k<2304, 2304, true, false>,
                         cudaFuncAttributeMaxDynamicSharedMemorySize, SM_FCS);
    cudaFuncSetAttribute((const void*)fc_batch_k<12288, 2048, false, true>,
                         cudaFuncAttributeMaxDynamicSharedMemorySize, SM_FCP);

    conv_in_k<36, false, false><<<1024, 256, SM_IN36>>>(x_s, Ws_in_W, Ws_in_b, nullptr, s1);
    conv_hid_k<32, 2><<<1024, 256, SM_H32>>>(s1, Ws_hid_W, Ws_hid_b, s2);
    conv_hid_k<16, 6><<<1024, 192, SM_H16>>>(s2, Ws_hid_W, Ws_hid_b, s3);
    conv_in_k<12, true, true><<<1024, 256, SM_IN12>>>(x_p, Pc_W, Pc_b, dom, p1);
    fc_batch_k<2304, 2304, true, false><<<64, 256, SM_FCS>>>(s3, Ws_fc_W, Ws_fc_b, nullptr, hb);
    fc_batch_k<12288, 2048, false, true><<<64, 256, SM_FCP>>>(p1, Pl_W, Pl_b, dom, pf);
    heads_k<<<4, 256>>>(hb, pf, tt, H1W, H1b, H2W, H2b, H3W, H3b, out);
}

// round 7
// speedup vs baseline: 1.2425x; 1.1255x over previous
#include <cuda_runtime.h>
#include <cuda_bf16.h>
#include <cstdint>

// ---------------------------------------------------------------------------
// tf32 helpers
// ---------------------------------------------------------------------------
__device__ __forceinline__ float tf32r(float f) {
    uint32_t o; asm("cvt.rna.tf32.f32 %0,%1;" : "=r"(o) : "f"(f));
    return __uint_as_float(o);
}
__device__ __forceinline__ void mma4(float* c, uint32_t a0, uint32_t a1, uint32_t b0) {
    asm("mma.sync.aligned.m16n8k4.row.col.f32.tf32.tf32.f32 "
        "{%0,%1,%2,%3},{%4,%5},{%6},{%0,%1,%2,%3};"
        : "+f"(c[0]), "+f"(c[1]), "+f"(c[2]), "+f"(c[3])
        : "r"(a0), "r"(a1), "r"(b0));
}
__device__ __forceinline__ uint32_t fbits(float f) { return __float_as_uint(f); }

// ---------------------------------------------------------------------------
// Scratch
// ---------------------------------------------------------------------------
__device__ float g_s1[1024 * 32 * 32 * 36];   // conv1 out, NHWC
__device__ float g_s2[1024 * 16 * 16 * 36];   // conv2 out, NHWC
__device__ float g_s3[1024 * 36 * 8 * 8];     // conv3 out, NCHW (flatten 2304)
__device__ float g_h [1024 * 12];
__device__ float g_p1[1024 * 12 * 32 * 32];   // private conv out, NCHW (12288)
__device__ float g_pf[1024 * 12];

// ---------------------------------------------------------------------------
// Epilogue: fragment-level 2x2 maxpool via shfl, bias+act, store.
// acc rows map: c0/c1 -> (dy=g>>2, dx=g&3, oc=2t / 2t+1), c2/c3 -> dy+2.
// ---------------------------------------------------------------------------
template <int OCR, int PO, bool LEAKY, bool NCHW_OUT>
__device__ __forceinline__ void epilogue_tile(const float acc[][4], int NF,
                                              int ty, int tx, int g, int t,
                                              const float* b_s, float* out) {
    for (int nf = 0; nf < NF; nf++) {
        float v0 = acc[nf][0], v1 = acc[nf][1], v2 = acc[nf][2], v3 = acc[nf][3];
        v0 = fmaxf(v0, __shfl_xor_sync(0xffffffffu, v0, 4));
        v1 = fmaxf(v1, __shfl_xor_sync(0xffffffffu, v1, 4));
        v2 = fmaxf(v2, __shfl_xor_sync(0xffffffffu, v2, 4));
        v3 = fmaxf(v3, __shfl_xor_sync(0xffffffffu, v3, 4));
        v0 = fmaxf(v0, __shfl_xor_sync(0xffffffffu, v0, 16));
        v1 = fmaxf(v1, __shfl_xor_sync(0xffffffffu, v1, 16));
        v2 = fmaxf(v2, __shfl_xor_sync(0xffffffffu, v2, 16));
        v3 = fmaxf(v3, __shfl_xor_sync(0xffffffffu, v3, 16));
        int oc = nf * 8 + 2 * t;
        if (((g & 1) == 0) && (g < 4) && oc < OCR) {
            int px  = tx * 2 + (g >> 1);
            int py0 = ty * 2;
            float b0 = b_s[oc], b1 = b_s[oc + 1];
            float o00 = v0 + b0, o01 = v1 + b1, o10 = v2 + b0, o11 = v3 + b1;
            if (LEAKY) {
                o00 = o00 > 0.f ? o00 : 0.001f * o00;
                o01 = o01 > 0.f ? o01 : 0.001f * o01;
                o10 = o10 > 0.f ? o10 : 0.001f * o10;
                o11 = o11 > 0.f ? o11 : 0.001f * o11;
            } else {
                o00 = fmaxf(o00, 0.f); o01 = fmaxf(o01, 0.f);
                o10 = fmaxf(o10, 0.f); o11 = fmaxf(o11, 0.f);
            }
            if (NCHW_OUT) {
                out[( oc      * PO + py0)     * PO + px] = o00;
                out[((oc + 1) * PO + py0)     * PO + px] = o01;
                out[( oc      * PO + py0 + 1) * PO + px] = o10;
                out[((oc + 1) * PO + py0 + 1) * PO + px] = o11;
            } else {
                *(float2*)&out[((py0    ) * PO + px) * OCR + oc] = make_float2(o00, o01);
                *(float2*)&out[((py0 + 1) * PO + px) * OCR + oc] = make_float2(o10, o11);
            }
        }
    }
}

// ---------------------------------------------------------------------------
// First-layer conv: Cin=3 (padded to 4 in NHWC smem), H=64, conv+bias+act+pool.
// x is NCHW global. K per shift = 4 (one k4-frag), 9 shifts.
// ---------------------------------------------------------------------------
template <int OCR, int OCP, bool LEAKY, bool USE_DOM, bool NCHW_OUT>
__global__ __launch_bounds__(256) void conv_first_k(const float* __restrict__ x,
                                                    const float* __restrict__ W,
                                                    const float* __restrict__ bias,
                                                    const int*   __restrict__ dom,
                                                    float* __restrict__ out) {
    constexpr int PITCH = 272;                 // 66*4 padded to %32==16
    constexpr int NF = OCP / 8;
    constexpr int TX = 16, NST = 128, PO = 32;
    extern __shared__ float smem[];
    float* in_s = smem;                        // 66*272
    float* Bs   = smem + 66 * PITCH;           // 9*OCP*4
    float* b_s  = Bs + 9 * OCP * 4;            // OCP

    int b = blockIdx.x, tid = threadIdx.x;
    if (USE_DOM) { int d = *dom; W += d * OCR * 27; bias += d * OCR; }

    for (int i = tid; i < 66 * PITCH; i += 256) in_s[i] = 0.f;
    __syncthreads();
    const float* src = x + (size_t)b * 3 * 4096;
    for (int i = tid; i < 3 * 4096; i += 256) {
        int c = i >> 12, y = (i >> 6) & 63, xx = i & 63;
        in_s[(y + 1) * PITCH + (xx + 1) * 4 + c] = tf32r(src[i]);
    }
    for (int i = tid; i < 9 * OCP * 4; i += 256) {
        int s = i / (OCP * 4), oc = (i >> 2) % OCP, c = i & 3;
        Bs[i] = (oc < OCR && c < 3) ? tf32r(W[oc * 27 + c * 9 + s]) : 0.f;
    }
    if (tid < OCP) b_s[tid] = (tid < OCR) ? bias[tid] : 0.f;
    __syncthreads();

    int lane = tid & 31, warp = tid >> 5;
    int g = lane >> 2, t = lane & 3;
    const float* ap  = in_s + (g >> 2) * PITCH + (g & 3) * 4 + t;
    const float* bp0 = Bs + g * 4 + t;
    float* ob = out + (size_t)b * OCR * PO * PO;

    for (int s = warp; s < NST; s += 8) {
        int ty = (2 * s) / TX, tx0 = (2 * s) % TX;
        const float* a0p = ap + (ty * 4) * PITCH + (tx0 * 4) * 4;
        float acc[2][NF][4];
        #pragma unroll
        for (int j = 0; j < 2; j++)
            #pragma unroll
            for (int nf = 0; nf < NF; nf++)
                #pragma unroll
                for (int q = 0; q < 4; q++) acc[j][nf][q] = 0.f;

        #pragma unroll
        for (int ky = 0; ky < 3; ky++)
            #pragma unroll
            for (int kx = 0; kx < 3; kx++) {
                const float* q = a0p + ky * PITCH + kx * 4;
                uint32_t a00 = fbits(q[0]);
                uint32_t a01 = fbits(q[2 * PITCH]);
                uint32_t a10 = fbits(q[16]);
                uint32_t a11 = fbits(q[2 * PITCH + 16]);
                const float* bb = bp0 + (ky * 3 + kx) * OCP * 4;
                #pragma unroll
                for (int nf = 0; nf < NF; nf++) {
                    uint32_t bv = fbits(bb[nf * 32]);
                    mma4(acc[0][nf], a00, a01, bv);
                    mma4(acc[1][nf], a10, a11, bv);
                }
            }
        epilogue_tile<OCR, PO, LEAKY, NCHW_OUT>(acc[0], NF, ty, tx0,     g, t, b_s, ob);
        epilogue_tile<OCR, PO, LEAKY, NCHW_OUT>(acc[1], NF, ty, tx0 + 1, g, t, b_s, ob);
    }
}

// ---------------------------------------------------------------------------
// Mid conv: 36->36, input NHWC global [HH][HH][36], conv+bias+relu+pool.
// K=36 = 9 k4-frags per shift, 9 shifts. OCP=40 (NF=5).
// ---------------------------------------------------------------------------
template <int HH, bool NCHW_OUT>
__global__ __launch_bounds__(256) void conv_mid_k(const float* __restrict__ in,
                                                  const float* __restrict__ W,
                                                  const float* __restrict__ bias,
                                                  float* __restrict__ out) {
    constexpr int PITCH = (HH == 32) ? 1232 : 656;   // (HH+2)*36 padded to %32==16
    constexpr int ROWS = HH + 2;
    constexpr int TX = HH / 4, NST = TX * TX / 2, PO = HH / 2;
    constexpr int NF = 5;
    extern __shared__ float smem[];
    float* in_s = smem;                        // ROWS*PITCH
    float* Bs   = smem + ROWS * PITCH;         // 9*40*36
    float* b_s  = Bs + 9 * 40 * 36;

    int b = blockIdx.x, tid = threadIdx.x;
    for (int i = tid; i < ROWS * PITCH; i += 256) in_s[i] = 0.f;
    __syncthreads();
    const float* src = in + (size_t)b * HH * HH * 36;
    for (int i = tid; i < HH * HH * 36; i += 256) {
        int p = i / 36, c = i % 36;
        int y = p / HH, xx = p % HH;
        in_s[(y + 1) * PITCH + (xx + 1) * 36 + c] = tf32r(src[i]);
    }
    for (int i = tid; i < 9 * 40 * 36; i += 256) {
        int s = i / 1440, oc = (i / 36) % 40, ic = i % 36;
        Bs[i] = (oc < 36) ? tf32r(W[oc * 324 + ic * 9 + s]) : 0.f;
    }
    if (tid < 40) b_s[tid] = (tid < 36) ? bias[tid] : 0.f;
    __syncthreads();

    int lane = tid & 31, warp = tid >> 5;
    int g = lane >> 2, t = lane & 3;
    const float* ap  = in_s + (g >> 2) * PITCH + (g & 3) * 36 + t;
    const float* bp0 = Bs + g * 36 + t;
    float* ob = out + (size_t)b * 36 * PO * PO;

    for (int s = warp; s < NST; s += 8) {
        int ty = (2 * s) / TX, tx0 = (2 * s) % TX;
        const float* a0p = ap + (ty * 4) * PITCH + (tx0 * 4) * 36;
        float acc[2][NF][4];
        #pragma unroll
        for (int j = 0; j < 2; j++)
            #pragma unroll
            for (int nf = 0; nf < NF; nf++)
                #pragma unroll
                for (int q = 0; q < 4; q++) acc[j][nf][q] = 0.f;

        #pragma unroll 1
        for (int sh = 0; sh < 9; sh++) {
            int ky = sh / 3, kx = sh % 3;
            const float* q0 = a0p + ky * PITCH + kx * 36;
            const float* bb = bp0 + sh * 1440;
            #pragma unroll
            for (int k4 = 0; k4 < 9; k4++) {
                const float* q = q0 + k4 * 4;
                uint32_t a00 = fbits(q[0]);
                uint32_t a01 = fbits(q[2 * PITCH]);
                uint32_t a10 = fbits(q[144]);
                uint32_t a11 = fbits(q[2 * PITCH + 144]);
                #pragma unroll
                for (int nf = 0; nf < NF; nf++) {
                    uint32_t bv = fbits(bb[nf * 288 + k4 * 4]);
                    mma4(acc[0][nf], a00, a01, bv);
                    mma4(acc[1][nf], a10, a11, bv);
                }
            }
        }
        epilogue_tile<36, PO, false, NCHW_OUT>(acc[0], NF, ty, tx0,     g, t, b_s, ob);
        epilogue_tile<36, PO, false, NCHW_OUT>(acc[1], NF, ty, tx0 + 1, g, t, b_s, ob);
    }
}

// ---------------------------------------------------------------------------
// Batched FC (fp32, full precision): 16 samples/block, W staged in SMEM.
// ---------------------------------------------------------------------------
template <int K, int KC, bool RELU, bool USE_DOM>
__global__ __launch_bounds__(256) void fc_batch_k(const float* __restrict__ in,
                                                  const float* __restrict__ W,
                                                  const float* __restrict__ bias,
                                                  const int*   __restrict__ dom,
                                                  float* __restrict__ out) {
    extern __shared__ float ws[];
    if (USE_DOM) { int d = *dom; W += (size_t)d * 12 * K; bias += d * 12; }
    int tid = threadIdx.x, lane = tid & 31, l16 = lane & 15;
    int s = (tid >> 5) * 2 + (lane >> 4);
    const float* xp = in + ((size_t)blockIdx.x * 16 + s) * K;

    float acc[12];
    #pragma unroll
    for (int o = 0; o < 12; o++) acc[o] = 0.f;

    for (int kc0 = 0; kc0 < K; kc0 += KC) {
        __syncthreads();
        for (int i = tid; i < 12 * KC; i += 256) {
            int o = i / KC, k = i % KC;
            ws[i] = W[(size_t)o * K + kc0 + k];
        }
        __syncthreads();
        constexpr int NI = KC / 64;
        #pragma unroll 4
        for (int i = 0; i < NI; i++) {
            int k4 = l16 + i * 16;
            float4 xa = ((const float4*)(xp + kc0))[k4];
            #pragma unroll
            for (int o = 0; o < 12; o++) {
                float4 wa = ((const float4*)(ws + o * KC))[k4];
                acc[o] = fmaf(xa.x, wa.x, fmaf(xa.y, wa.y,
                          fmaf(xa.z, wa.z, fmaf(xa.w, wa.w, acc[o]))));
            }
        }
    }
    #pragma unroll
    for (int o = 0; o < 12; o++) {
        #pragma unroll
        for (int off = 8; off; off >>= 1)
            acc[o] += __shfl_down_sync(0xffffffffu, acc[o], off, 16);
    }
    if (l16 == 0) {
        size_t sg = (size_t)blockIdx.x * 16 + s;
        #pragma unroll
        for (int o = 0; o < 12; o++) {
            float v = acc[o] + bias[o];
            out[sg * 12 + o] = RELU ? fmaxf(v, 0.f) : v;
        }
    }
}

// ---------------------------------------------------------------------------
// Per-sample task-routed heads.
// ---------------------------------------------------------------------------
__global__ void heads_k(const float* __restrict__ h, const float* __restrict__ p,
                        const int* __restrict__ tt,
                        const float* __restrict__ W1, const float* __restrict__ b1,
                        const float* __restrict__ W2, const float* __restrict__ b2,
                        const float* __restrict__ W3, const float* __restrict__ b3,
                        float* __restrict__ out) {
    int bi = blockIdx.x * blockDim.x + threadIdx.x;
    if (bi >= 1024) return;
    int t = tt[bi];
    float x[24];
    #pragma unroll
    for (int i = 0; i < 12; i++) { x[i] = h[bi * 12 + i]; x[12 + i] = p[bi * 12 + i]; }
    float h1[28];
    const float* w1 = W1 + t * 28 * 24;
    #pragma unroll
    for (int i = 0; i < 28; i++) {
        float s = b1[t * 28 + i];
        #pragma unroll
        for (int j = 0; j < 24; j++) s = fmaf(w1[i * 24 + j], x[j], s);
        h1[i] = fmaxf(s, 0.f);
    }
    float h2[14];
    const float* w2 = W2 + t * 14 * 28;
    #pragma unroll
    for (int i = 0; i < 14; i++) {
        float s = b2[t * 14 + i];
        #pragma unroll
        for (int j = 0; j < 28; j++) s = fmaf(w2[i * 28 + j], h1[j], s);
        h2[i] = fmaxf(s, 0.f);
    }
    const float* w3 = W3 + t * 5 * 14;
    #pragma unroll
    for (int i = 0; i < 5; i++) {
        float s = b3[t * 5 + i];
        #pragma unroll
        for (int j = 0; j < 14; j++) s = fmaf(w3[i * 14 + j], h2[j], s);
        out[bi * 5 + i] = s;
    }
}

// ---------------------------------------------------------------------------
// Launch
// ---------------------------------------------------------------------------
extern "C" void kernel_launch(void* const* d_in, const int* in_sizes, int n_in,
                              void* d_out, int out_size) {
    const float* x_s      = (const float*)d_in[0];
    const float* x_p      = (const float*)d_in[1];
    const int*   tt       = (const int*)  d_in[2];
    const int*   dom      = (const int*)  d_in[3];
    const float* Ws_in_W  = (const float*)d_in[4];
    const float* Ws_in_b  = (const float*)d_in[5];
    const float* Ws_hid_W = (const float*)d_in[6];
    const float* Ws_hid_b = (const float*)d_in[7];
    const float* Ws_fc_W  = (const float*)d_in[8];
    const float* Ws_fc_b  = (const float*)d_in[9];
    const float* Pc_W     = (const float*)d_in[10];
    const float* Pc_b     = (const float*)d_in[11];
    const float* Pl_W     = (const float*)d_in[12];
    const float* Pl_b     = (const float*)d_in[13];
    const float* H1W      = (const float*)d_in[14];
    const float* H1b      = (const float*)d_in[15];
    const float* H2W      = (const float*)d_in[16];
    const float* H2b      = (const float*)d_in[17];
    const float* H3W      = (const float*)d_in[18];
    const float* H3b      = (const float*)d_in[19];
    float* out = (float*)d_out;

    float *s1, *s2, *s3, *hb, *p1, *pf;
    cudaGetSymbolAddress((void**)&s1, g_s1);
    cudaGetSymbolAddress((void**)&s2, g_s2);
    cudaGetSymbolAddress((void**)&s3, g_s3);
    cudaGetSymbolAddress((void**)&hb, g_h);
    cudaGetSymbolAddress((void**)&p1, g_p1);
    cudaGetSymbolAddress((void**)&pf, g_pf);

    const int SM_C1 = (66 * 272 + 9 * 40 * 4 + 40) * 4;          // 77728
    const int SM_CP = (66 * 272 + 9 * 16 * 4 + 16) * 4;          // 74176
    const int SM_C2 = (34 * 1232 + 9 * 40 * 36 + 40) * 4;        // 219552
    const int SM_C3 = (18 * 656  + 9 * 40 * 36 + 40) * 4;        // 99232
    const int SM_FCS = 12 * 2304 * 4;                            // 110592
    const int SM_FCP = 12 * 2048 * 4;                            // 98304

    cudaFuncSetAttribute((const void*)conv_first_k<36, 40, false, false, false>,
                         cudaFuncAttributeMaxDynamicSharedMemorySize, SM_C1);
    cudaFuncSetAttribute((const void*)conv_first_k<12, 16, true, true, true>,
                         cudaFuncAttributeMaxDynamicSharedMemorySize, SM_CP);
    cudaFuncSetAttribute((const void*)conv_mid_k<32, false>,
                         cudaFuncAttributeMaxDynamicSharedMemorySize, SM_C2);
    cudaFuncSetAttribute((const void*)conv_mid_k<16, true>,
                         cudaFuncAttributeMaxDynamicSharedMemorySize, SM_C3);
    cudaFuncSetAttribute((const void*)fc_batch_k<2304, 2304, true, false>,
                         cudaFuncAttributeMaxDynamicSharedMemorySize, SM_FCS);
    cudaFuncSetAttribute((const void*)fc_batch_k<12288, 2048, false, true>,
                         cudaFuncAttributeMaxDynamicSharedMemorySize, SM_FCP);

    // Shared branch: conv1 (NHWC out) -> conv2 (NHWC out) -> conv3 (NCHW out) -> fc
    conv_first_k<36, 40, false, false, false><<<1024, 256, SM_C1>>>(x_s, Ws_in_W, Ws_in_b, nullptr, s1);
    conv_mid_k<32, false><<<1024, 256, SM_C2>>>(s1, Ws_hid_W, Ws_hid_b, s2);
    conv_mid_k<16, true><<<1024, 256, SM_C3>>>(s2, Ws_hid_W, Ws_hid_b, s3);
    // Private branch: conv (NCHW out) -> fc
    conv_first_k<12, 16, true, true, true><<<1024, 256, SM_CP>>>(x_p, Pc_W, Pc_b, dom, p1);
    fc_batch_k<2304, 2304, true, false><<<64, 256, SM_FCS>>>(s3, Ws_fc_W, Ws_fc_b, nullptr, hb);
    fc_batch_k<12288, 2048, false, true><<<64, 256, SM_FCP>>>(p1, Pl_W, Pl_b, dom, pf);
    heads_k<<<4, 256>>>(hb, pf, tt, H1W, H1b, H2W, H2b, H3W, H3b, out);
}